// round 4
// baseline (speedup 1.0000x reference)
#include <cuda_runtime.h>
#include <cuda_fp16.h>

// out[b,o] = min_i max(x[b,i], w[i,o])   (forward of STE expr == hard min-max)
//
// Sorted-scan with PER-LANE pruning: candidates i processed in increasing
// x[b,i] (256-bin bucket order). A lane owning 4 o's retires as soon as
// bin_floor(next x) >= max of its 4 current bests: every remaining candidate
// has x_i >= bound >= best, so max(x_i, w) >= best -- exact result guaranteed,
// independent of within-bin order. Retired lanes issue no more LDGs (their
// L2 sectors stop being fetched); a warp exits when all 32 lanes retire.
//
// fp16 inputs (RN) bound rel err by ~2^-11 < 1e-3.

#define DB 512
#define DI 512
#define DO 1024
#define NBIN 256

__device__ __half g_wh[DI * DO];      // fp16 w, 1 MB
__device__ uint2  g_xsort[DB * DI];   // per-b bin-ordered {dup-h2(x), idx}, 2 MB

// ---------- Kernel A (fused prep): blocks [0,512) sort x rows, [512,640) convert w ----------
__global__ __launch_bounds__(256) void k_prep(const float* __restrict__ x,
                                              const float* __restrict__ w) {
    const int tid = threadIdx.x;

    if (blockIdx.x >= DB) {
        // ---- convert w -> fp16, 128 blocks, 4 float4s per thread (MLP=4) ----
        const int c = blockIdx.x - DB;
        float4 v[4];
#pragma unroll
        for (int e = 0; e < 4; e++)
            v[e] = reinterpret_cast<const float4*>(w)[c * 1024 + e * 256 + tid];
#pragma unroll
        for (int e = 0; e < 4; e++) {
            __half2 h0 = __floats2half2_rn(v[e].x, v[e].y);
            __half2 h1 = __floats2half2_rn(v[e].z, v[e].w);
            reinterpret_cast<uint2*>(g_wh)[c * 1024 + e * 256 + tid] =
                make_uint2(*reinterpret_cast<unsigned*>(&h0),
                           *reinterpret_cast<unsigned*>(&h1));
        }
        return;
    }

    // ---- 256-bin counting sort of x[b,:] by value ----
    __shared__ int hist[NBIN];
    __shared__ int offs[NBIN];
    __shared__ int wsum[8];
    const int b = blockIdx.x;
    const int lane = tid & 31, wid = tid >> 5;

    hist[tid] = 0;
    __syncthreads();

    __half h[2]; int bin[2];
#pragma unroll
    for (int e = 0; e < 2; e++) {
        int i = tid + e * 256;
        h[e] = __float2half_rn(x[b * DI + i]);
        float vf = __half2float(h[e]);
        bin[e] = min(NBIN - 1, (int)(vf * (float)NBIN));
        atomicAdd(&hist[bin[e]], 1);
    }
    __syncthreads();

    // parallel exclusive prefix over 256 bins (thread t owns bin t)
    int v = hist[tid];
#pragma unroll
    for (int off = 1; off < 32; off <<= 1) {
        int n = __shfl_up_sync(0xffffffffu, v, off);
        if (lane >= off) v += n;
    }
    if (lane == 31) wsum[wid] = v;
    __syncthreads();
    if (tid < 8) {
        int s = wsum[tid];
#pragma unroll
        for (int off = 1; off < 8; off <<= 1) {
            int n = __shfl_up_sync(0xffu, s, off);
            if (tid >= off) s += n;
        }
        wsum[tid] = s;
    }
    __syncthreads();
    int incl = v + (wid ? wsum[wid - 1] : 0);
    offs[tid] = incl - hist[tid];     // exclusive prefix
    __syncthreads();

#pragma unroll
    for (int e = 0; e < 2; e++) {
        int i = tid + e * 256;
        int p = atomicAdd(&offs[bin[e]], 1);
        unsigned hh = (unsigned)__half_as_ushort(h[e]);
        g_xsort[b * DI + p] = make_uint2(hh | (hh << 16), (unsigned)i);
    }
}

// ---------- Kernel B: pruned scan, per-lane retirement ----------
__global__ __launch_bounds__(256) void k_main(float* __restrict__ out) {
    __shared__ uint2 sx[DI];   // 4 KB bin-ordered candidates

    const int b = blockIdx.x;
    const int tid = threadIdx.x;
    const int lane = tid & 31, wid = tid >> 5;

    sx[tid]       = g_xsort[b * DI + tid];
    sx[tid + 256] = g_xsort[b * DI + tid + 256];
    __syncthreads();

    const unsigned infu = 0x7C007C00u;   // {+inf,+inf} fp16
    __half2 best0 = *reinterpret_cast<const __half2*>(&infu);
    __half2 best1 = best0;

    // this thread owns o = wid*128 + lane*4 .. +3
    const __half* wb = g_wh + wid * 128 + lane * 4;

    bool done = false;
    for (int k = 0; k < DI; k += 8) {
        if (k) {
            // conservative lower bound for all candidates at position >= k:
            // they live in the same-or-later bin, so value >= bin_floor.
            unsigned nx = sx[k].x & 0xFFFFu;
            float nv = __half2float(__ushort_as_half((unsigned short)nx));
            int nbin = min(NBIN - 1, (int)(nv * (float)NBIN));
            float bound = (float)nbin * (1.0f / (float)NBIN);
            if (!done) {
                __half2 m2 = __hmax2(best0, best1);
                float m = fmaxf(__low2float(m2), __high2float(m2));
                done = (bound >= m);
            }
            if (!__ballot_sync(0xffffffffu, !done)) break;
        }
#pragma unroll
        for (int kk = 0; kk < 8; kk++) {
            if (!done) {
                uint2 e = sx[k + kk];
                __half2 xv = *reinterpret_cast<__half2*>(&e.x);
                uint2 wv = *reinterpret_cast<const uint2*>(wb + (e.y << 10));
                best0 = __hmin2(best0, __hmax2(xv, *reinterpret_cast<__half2*>(&wv.x)));
                best1 = __hmin2(best1, __hmax2(xv, *reinterpret_cast<__half2*>(&wv.y)));
            }
        }
    }

    float4 r;
    r.x = __low2float(best0);  r.y = __high2float(best0);
    r.z = __low2float(best1);  r.w = __high2float(best1);
    *reinterpret_cast<float4*>(&out[b * DO + wid * 128 + lane * 4]) = r;
}

extern "C" void kernel_launch(void* const* d_in, const int* in_sizes, int n_in,
                              void* d_out, int out_size) {
    const float* x = (const float*)d_in[0];   // [512, 512]
    const float* w = (const float*)d_in[1];   // [512, 1024]
    float* out = (float*)d_out;               // [512, 1024]

    k_prep<<<DB + 128, 256>>>(x, w);   // 512 sort blocks + 128 convert blocks
    k_main<<<DB, 256>>>(out);          // one block per batch row
}

// round 6
// speedup vs baseline: 1.7127x; 1.7127x over previous
#include <cuda_runtime.h>
#include <cuda_fp16.h>

// out[b,o] = min_i max(x[b,i], w[i,o])   (forward of STE expr == hard min-max)
//
// Sorted-scan with WARP-uniform pruning: candidates i processed in increasing
// x[b,i] (256-bin bucket order). A warp owning 128 o's exits when
// bin_floor(next x) >= max over its lanes' bests: every remaining candidate
// has x_i >= bound >= best, so max(x_i,w) >= best -- exact result, independent
// of within-bin order. The exit branch is warp-uniform, so the unrolled gather
// body stays UNPREDICATED -> ptxas front-batches the 16 LDGs (MLP~16).
// (R4 lesson: per-lane predication collapsed MLP to ~1 and doubled runtime.)
//
// fp16 inputs (RN) bound rel err by ~2^-11 < 1e-3.

#define DB 512
#define DI 512
#define DO 1024
#define NBIN 256

__device__ __half g_wh[DI * DO];      // fp16 w, 1 MB
__device__ uint2  g_xsort[DB * DI];   // per-b bin-ordered {dup-h2(x), idx}, 2 MB

// ---------- Kernel A (fused prep): blocks [0,512) sort x rows, [512,640) convert w ----------
__global__ __launch_bounds__(256) void k_prep(const float* __restrict__ x,
                                              const float* __restrict__ w) {
    const int tid = threadIdx.x;

    if (blockIdx.x >= DB) {
        // ---- convert w -> fp16, 128 blocks, 4 float4s per thread (MLP=4) ----
        const int c = blockIdx.x - DB;
        float4 v[4];
#pragma unroll
        for (int e = 0; e < 4; e++)
            v[e] = reinterpret_cast<const float4*>(w)[c * 1024 + e * 256 + tid];
#pragma unroll
        for (int e = 0; e < 4; e++) {
            __half2 h0 = __floats2half2_rn(v[e].x, v[e].y);
            __half2 h1 = __floats2half2_rn(v[e].z, v[e].w);
            reinterpret_cast<uint2*>(g_wh)[c * 1024 + e * 256 + tid] =
                make_uint2(*reinterpret_cast<unsigned*>(&h0),
                           *reinterpret_cast<unsigned*>(&h1));
        }
        return;
    }

    // ---- 256-bin counting sort of x[b,:] by value ----
    __shared__ int hist[NBIN];
    __shared__ int offs[NBIN];
    __shared__ int wsum[8];
    const int b = blockIdx.x;
    const int lane = tid & 31, wid = tid >> 5;

    hist[tid] = 0;
    __syncthreads();

    __half h[2]; int bin[2];
#pragma unroll
    for (int e = 0; e < 2; e++) {
        int i = tid + e * 256;
        h[e] = __float2half_rn(x[b * DI + i]);
        float vf = __half2float(h[e]);
        bin[e] = min(NBIN - 1, (int)(vf * (float)NBIN));
        atomicAdd(&hist[bin[e]], 1);
    }
    __syncthreads();

    // parallel exclusive prefix over 256 bins (thread t owns bin t)
    int v = hist[tid];
#pragma unroll
    for (int off = 1; off < 32; off <<= 1) {
        int n = __shfl_up_sync(0xffffffffu, v, off);
        if (lane >= off) v += n;
    }
    if (lane == 31) wsum[wid] = v;
    __syncthreads();
    if (tid < 8) {
        int s = wsum[tid];
#pragma unroll
        for (int off = 1; off < 8; off <<= 1) {
            int n = __shfl_up_sync(0xffu, s, off);
            if (tid >= off) s += n;
        }
        wsum[tid] = s;
    }
    __syncthreads();
    int incl = v + (wid ? wsum[wid - 1] : 0);
    offs[tid] = incl - hist[tid];     // exclusive prefix
    __syncthreads();

#pragma unroll
    for (int e = 0; e < 2; e++) {
        int i = tid + e * 256;
        int p = atomicAdd(&offs[bin[e]], 1);
        unsigned hh = (unsigned)__half_as_ushort(h[e]);
        g_xsort[b * DI + p] = make_uint2(hh | (hh << 16), (unsigned)i);
    }
}

// ---------- Kernel B: pruned scan, warp-level retirement, unpredicated body ----------
__global__ __launch_bounds__(256) void k_main(float* __restrict__ out) {
    __shared__ uint2 sx[DI];   // 4 KB bin-ordered candidates

    const int b = blockIdx.x;
    const int tid = threadIdx.x;
    const int lane = tid & 31, wid = tid >> 5;

    // preload candidates: 2x LDS.128-wide stores (uint4 = two sx entries)
    {
        const uint4* src = reinterpret_cast<const uint4*>(g_xsort + b * DI);
        uint4* dst = reinterpret_cast<uint4*>(sx);
        dst[tid] = src[tid];                    // covers sx[0..511] as 256 uint4
    }
    __syncthreads();

    const unsigned infu = 0x7C007C00u;   // {+inf,+inf} fp16
    __half2 best0 = *reinterpret_cast<const __half2*>(&infu);
    __half2 best1 = best0;

    // this thread owns o = wid*128 + lane*4 .. +3 ; warp owns 128 contiguous o
    const __half* wb = g_wh + wid * 128 + lane * 4;

    for (int k = 0; k < DI; k += 16) {
        if (k) {
            // conservative lower bound for all candidates at position >= k:
            // sorted by bin, so value >= bin_floor(value at position k).
            // (computed first so the LDS overlaps the accumulator reduction)
            unsigned nx = sx[k].x & 0xFFFFu;
            float nv = __half2float(__ushort_as_half((unsigned short)nx));
            int nbin = min(NBIN - 1, (int)(nv * (float)NBIN));
            float bound = (float)nbin * (1.0f / (float)NBIN);
            __half2 m2 = __hmax2(best0, best1);
            float m = fmaxf(__low2float(m2), __high2float(m2));
            if (__all_sync(0xffffffffu, bound >= m)) break;   // warp-uniform exit
        }
        // unpredicated, fully unrolled gather body -> LDGs front-batched
#pragma unroll
        for (int kk = 0; kk < 16; kk++) {
            uint2 e = sx[k + kk];
            __half2 xv = *reinterpret_cast<__half2*>(&e.x);
            uint2 wv = *reinterpret_cast<const uint2*>(wb + (e.y << 10));
            best0 = __hmin2(best0, __hmax2(xv, *reinterpret_cast<__half2*>(&wv.x)));
            best1 = __hmin2(best1, __hmax2(xv, *reinterpret_cast<__half2*>(&wv.y)));
        }
    }

    float4 r;
    r.x = __low2float(best0);  r.y = __high2float(best0);
    r.z = __low2float(best1);  r.w = __high2float(best1);
    *reinterpret_cast<float4*>(&out[b * DO + wid * 128 + lane * 4]) = r;
}

extern "C" void kernel_launch(void* const* d_in, const int* in_sizes, int n_in,
                              void* d_out, int out_size) {
    const float* x = (const float*)d_in[0];   // [512, 512]
    const float* w = (const float*)d_in[1];   // [512, 1024]
    float* out = (float*)d_out;               // [512, 1024]

    k_prep<<<DB + 128, 256>>>(x, w);   // 512 sort blocks + 128 convert blocks
    k_main<<<DB, 256>>>(out);          // one block per batch row
}